// round 11
// baseline (speedup 1.0000x reference)
#include <cuda_runtime.h>
#include <math.h>
#include <stdint.h>

#define NTOK   2048
#define DMODEL 256
#define DFF    1024
#define NHEAD  8
#define DHEAD  32
#define KWIN   5
#define NNBR   125   // 5*5*5

#define NBLK   148   // persistent grid: 1 block per SM, guaranteed co-resident
#define NTHR   512

// ---------------- scratch (device globals; no allocations allowed) ----------
__device__ float g_q [NTOK * DMODEL];
__device__ float g_k [NTOK * DMODEL];
__device__ float g_v [NTOK * DMODEL];
__device__ float g_at[NTOK * DMODEL];
__device__ float g_h [NTOK * DMODEL];
__device__ float g_fa[NTOK * DFF];
__device__ float g_rs1[NTOK];
__device__ float g_ssp[8 * NTOK];     // per-row sumsq partials of h (8 col-slices)
__device__ unsigned g_ctr[8];         // grid-sync counters (monotonic, replay-safe)

// ---------------- helpers ----------------------------------------------------
__device__ __forceinline__ void mma_tf32(float d[4], const uint32_t a[4], const uint32_t b[2]) {
    asm volatile(
        "mma.sync.aligned.m16n8k8.row.col.f32.tf32.tf32.f32 "
        "{%0,%1,%2,%3},{%4,%5,%6,%7},{%8,%9},{%0,%1,%2,%3};"
        : "+f"(d[0]), "+f"(d[1]), "+f"(d[2]), "+f"(d[3])
        : "r"(a[0]), "r"(a[1]), "r"(a[2]), "r"(a[3]), "r"(b[0]), "r"(b[1]));
}

__device__ __forceinline__ void cp_async16(void* smem_dst, const void* gsrc) {
    uint32_t s = (uint32_t)__cvta_generic_to_shared(smem_dst);
    asm volatile("cp.async.cg.shared.global [%0], [%1], 16;" :: "r"(s), "l"(gsrc));
}
__device__ __forceinline__ void cp_commit() { asm volatile("cp.async.commit_group;"); }

__device__ __forceinline__ void bar_sync(int id, int cnt) {
    asm volatile("bar.sync %0, %1;" :: "r"(id), "r"(cnt) : "memory");
}

__device__ __forceinline__ void grid_sync(int ph) {
    __syncthreads();
    if (threadIdx.x == 0) {
        __threadfence();
        const unsigned old = atomicAdd(&g_ctr[ph], 1u);
        const unsigned target = (old / gridDim.x + 1u) * gridDim.x;
        while (*((volatile unsigned*)&g_ctr[ph]) < target) { }
        __threadfence();
    }
    __syncthreads();
}

#define ASTR 36   // A frag banks: 4g+tig -> permutation, conflict-free
#define BSTR 72   // B frag banks: 8tig+g -> permutation, conflict-free
#define NSTG 3    // pipeline stages

#define GEMM_WG_FLOATS (DMODEL + 32 + NSTG * 32 * ASTR + NSTG * 32 * BSTR)        // 10656
#define GATE_GR_FLOATS (DMODEL + 64 + NSTG * 64 * ASTR + 2 * NSTG * 32 * BSTR)    // 21056
#define SMEM_FLOATS    (4 * GEMM_WG_FLOATS)                                        // 42624 (max region)

// ---------------- GEMM tile (proven v7 body; named-barrier warpgroup) --------
template<bool SCALED>
__device__ void gemm_tile(
    int bx, int by, int barid, int tid_l,
    const float* __restrict__ A, const float* __restrict__ rs, const float* __restrict__ nw,
    const float* __restrict__ B, const float* __restrict__ bias, const float* __restrict__ res,
    float* __restrict__ C, float* __restrict__ ssp,
    int N, int K, float* wsm) {

    float* nws = wsm;                       // 256
    float* rsc = wsm + DMODEL;              // 32
    float* Asm = rsc + 32;                  // NSTG * 32*ASTR
    float* Bsm = Asm + NSTG * 32 * ASTR;    // NSTG * 32*BSTR

    const int warp = tid_l >> 5;
    const int lane = tid_l & 31;
    const int g    = lane >> 2;
    const int tig  = lane & 3;
    const int warpRow = (warp & 1) * 16;
    const int warpCol = (warp >> 1) * 32;
    const int bm = by * 32;
    const int bn = bx * 64;

    float sc0 = 1.f, sc1 = 1.f;
    if (SCALED) {
        for (int i = tid_l * 4; i < K; i += 512)
            *(float4*)&nws[i] = *(const float4*)&nw[i];
        if (tid_l < 32) rsc[tid_l] = rs[bm + tid_l];
        bar_sync(barid, 128);
        sc0 = rsc[warpRow + g];
        sc1 = rsc[warpRow + g + 8];
    }

    float acc[4][4];
    #pragma unroll
    for (int nt = 0; nt < 4; nt++)
        #pragma unroll
        for (int i = 0; i < 4; i++) acc[nt][i] = 0.f;

    const int nkt = K >> 5;

    auto load_tile = [&](int st, int k0) {
        float* Ad = Asm + st * 32 * ASTR;
        float* Bd = Bsm + st * 32 * BSTR;
        #pragma unroll
        for (int j = 0; j < 2; j++) {          // A: 256 float4 chunks
            const int c = tid_l + 128 * j;
            const int row = c >> 3, kc = (c & 7) * 4;
            cp_async16(&Ad[row * ASTR + kc], &A[(size_t)(bm + row) * K + k0 + kc]);
        }
        #pragma unroll
        for (int j = 0; j < 4; j++) {          // B: 512 float4 chunks
            const int c = tid_l + 128 * j;
            const int row = c >> 4, nc = (c & 15) * 4;
            cp_async16(&Bd[row * BSTR + nc], &B[(size_t)(k0 + row) * N + bn + nc]);
        }
        cp_commit();
    };

    load_tile(0, 0);
    load_tile(1, 32);

    for (int kt = 0; kt < nkt; kt++) {
        const int st = kt % NSTG;
        if (kt + 2 < nkt) load_tile((kt + 2) % NSTG, (kt + 2) * 32);
        if (kt + 2 < nkt)      asm volatile("cp.async.wait_group 2;");
        else if (kt + 1 < nkt) asm volatile("cp.async.wait_group 1;");
        else                   asm volatile("cp.async.wait_group 0;");
        bar_sync(barid, 128);

        const float* Ab = Asm + st * 32 * ASTR;
        const float* Bb = Bsm + st * 32 * BSTR;
        const int kb = kt * 32;
        #pragma unroll
        for (int s = 0; s < 4; s++) {
            const int r0 = warpRow + g;
            float a0 = Ab[r0 * ASTR + 8 * s + tig];
            float a1 = Ab[(r0 + 8) * ASTR + 8 * s + tig];
            float a2 = Ab[r0 * ASTR + 8 * s + 4 + tig];
            float a3 = Ab[(r0 + 8) * ASTR + 8 * s + 4 + tig];
            if (SCALED) {
                const float w0 = nws[kb + 8 * s + tig];
                const float w1 = nws[kb + 8 * s + 4 + tig];
                a0 *= sc0 * w0; a1 *= sc1 * w0; a2 *= sc0 * w1; a3 *= sc1 * w1;
            }
            uint32_t ua[4] = {__float_as_uint(a0), __float_as_uint(a1),
                              __float_as_uint(a2), __float_as_uint(a3)};
            uint32_t b[4][2];
            #pragma unroll
            for (int nt = 0; nt < 4; nt++) {
                const int c = warpCol + nt * 8 + g;
                b[nt][0] = __float_as_uint(Bb[(8 * s + tig) * BSTR + c]);
                b[nt][1] = __float_as_uint(Bb[(8 * s + 4 + tig) * BSTR + c]);
            }
            #pragma unroll
            for (int nt = 0; nt < 4; nt++) mma_tf32(acc[nt], ua, b[nt]);
        }
        bar_sync(barid, 128);
    }

    const int r0 = bm + warpRow + g;
    const int r1 = r0 + 8;
    float s0 = 0.f, s1 = 0.f;
    #pragma unroll
    for (int nt = 0; nt < 4; nt++) {
        const int col = bn + warpCol + nt * 8 + 2 * tig;
        float b0 = 0.f, b1 = 0.f;
        if (bias) { b0 = bias[col]; b1 = bias[col + 1]; }
        float2 o0 = make_float2(acc[nt][0] + b0, acc[nt][1] + b1);
        float2 o1 = make_float2(acc[nt][2] + b0, acc[nt][3] + b1);
        if (res) {
            const float2 q0 = *(const float2*)&res[(size_t)r0 * N + col];
            const float2 q1 = *(const float2*)&res[(size_t)r1 * N + col];
            o0.x += q0.x; o0.y += q0.y;
            o1.x += q1.x; o1.y += q1.y;
        }
        s0 += o0.x * o0.x + o0.y * o0.y;
        s1 += o1.x * o1.x + o1.y * o1.y;
        *(float2*)&C[(size_t)r0 * N + col] = o0;
        *(float2*)&C[(size_t)r1 * N + col] = o1;
    }
    if (ssp) {
        s0 += __shfl_xor_sync(0xffffffffu, s0, 1);
        s0 += __shfl_xor_sync(0xffffffffu, s0, 2);
        s1 += __shfl_xor_sync(0xffffffffu, s1, 1);
        s1 += __shfl_xor_sync(0xffffffffu, s1, 2);
        if (tig == 0) {
            const int p = bx * 2 + (warp >> 1);   // 0..7 distinct col slices
            ssp[p * NTOK + r0] = s0;
            ssp[p * NTOK + r1] = s1;
        }
    }
}

// ---------------- gate tile (v8 body; 256-thread group) ----------------------
__device__ void gate_tile(
    int bx, int by, int barid, int tid_g,
    const float* __restrict__ A,
    const float* __restrict__ ssp, const float* __restrict__ nw,
    const float* __restrict__ W1, const float* __restrict__ W2,
    float* __restrict__ C, int N, int K, float* gsm) {

    float* nws = gsm;                       // 256
    float* rsc = gsm + DMODEL;              // 64
    float* Asm = rsc + 64;                  // NSTG * 64*ASTR
    float* B1m = Asm + NSTG * 64 * ASTR;    // NSTG * 32*BSTR
    float* B2m = B1m + NSTG * 32 * BSTR;    // NSTG * 32*BSTR

    const int warp = tid_g >> 5;
    const int lane = tid_g & 31;
    const int g    = lane >> 2;
    const int tig  = lane & 3;
    const int warpRow = (warp & 1) * 32;
    const int warpCol = (warp >> 1) * 16;
    const int bm = by * 64;
    const int bn = bx * 64;

    for (int i = tid_g * 4; i < K; i += 1024)
        *(float4*)&nws[i] = *(const float4*)&nw[i];
    if (tid_g < 64) {
        const int row = bm + tid_g;
        float s = 0.f;
        #pragma unroll
        for (int p = 0; p < 8; p++) s += ssp[p * NTOK + row];
        rsc[tid_g] = rsqrtf(s * (1.0f / DMODEL) + 1e-6f);
    }
    bar_sync(barid, 256);
    float sc[2][2];
    #pragma unroll
    for (int mt = 0; mt < 2; mt++) {
        sc[mt][0] = rsc[warpRow + mt * 16 + g];
        sc[mt][1] = rsc[warpRow + mt * 16 + g + 8];
    }

    float acc1[2][2][4], acc2[2][2][4];
    #pragma unroll
    for (int mt = 0; mt < 2; mt++)
        #pragma unroll
        for (int nt = 0; nt < 2; nt++)
            #pragma unroll
            for (int i = 0; i < 4; i++) { acc1[mt][nt][i] = 0.f; acc2[mt][nt][i] = 0.f; }

    const int nkt = K >> 5;

    auto load_tile = [&](int st, int k0) {
        float* Ad  = Asm + st * 64 * ASTR;
        float* B1d = B1m + st * 32 * BSTR;
        float* B2d = B2m + st * 32 * BSTR;
        #pragma unroll
        for (int j = 0; j < 2; j++) {          // A: 512 float4 chunks
            const int c = tid_g + 256 * j;
            const int row = c >> 3, kc = (c & 7) * 4;
            cp_async16(&Ad[row * ASTR + kc], &A[(size_t)(bm + row) * K + k0 + kc]);
        }
        #pragma unroll
        for (int j = 0; j < 2; j++) {          // B1,B2: 512 chunks each
            const int c = tid_g + 256 * j;
            const int row = c >> 4, nc = (c & 15) * 4;
            const size_t off = (size_t)(k0 + row) * N + bn + nc;
            cp_async16(&B1d[row * BSTR + nc], &W1[off]);
            cp_async16(&B2d[row * BSTR + nc], &W2[off]);
        }
        cp_commit();
    };

    load_tile(0, 0);
    load_tile(1, 32);

    for (int kt = 0; kt < nkt; kt++) {
        const int st = kt % NSTG;
        if (kt + 2 < nkt) load_tile((kt + 2) % NSTG, (kt + 2) * 32);
        if (kt + 2 < nkt)      asm volatile("cp.async.wait_group 2;");
        else if (kt + 1 < nkt) asm volatile("cp.async.wait_group 1;");
        else                   asm volatile("cp.async.wait_group 0;");
        bar_sync(barid, 256);

        const float* Ab  = Asm + st * 64 * ASTR;
        const float* B1b = B1m + st * 32 * BSTR;
        const float* B2b = B2m + st * 32 * BSTR;
        const int kb = kt * 32;
        #pragma unroll
        for (int s = 0; s < 4; s++) {
            const float w0 = nws[kb + 8 * s + tig];
            const float w1 = nws[kb + 8 * s + 4 + tig];
            uint32_t ua[2][4];
            #pragma unroll
            for (int mt = 0; mt < 2; mt++) {
                const int r0 = warpRow + mt * 16 + g;
                float a0 = Ab[r0 * ASTR + 8 * s + tig];
                float a1 = Ab[(r0 + 8) * ASTR + 8 * s + tig];
                float a2 = Ab[r0 * ASTR + 8 * s + 4 + tig];
                float a3 = Ab[(r0 + 8) * ASTR + 8 * s + 4 + tig];
                a0 *= sc[mt][0] * w0; a1 *= sc[mt][1] * w0;
                a2 *= sc[mt][0] * w1; a3 *= sc[mt][1] * w1;
                ua[mt][0] = __float_as_uint(a0); ua[mt][1] = __float_as_uint(a1);
                ua[mt][2] = __float_as_uint(a2); ua[mt][3] = __float_as_uint(a3);
            }
            uint32_t b1[2][2], b2[2][2];
            #pragma unroll
            for (int nt = 0; nt < 2; nt++) {
                const int c = warpCol + nt * 8 + g;
                b1[nt][0] = __float_as_uint(B1b[(8 * s + tig) * BSTR + c]);
                b1[nt][1] = __float_as_uint(B1b[(8 * s + 4 + tig) * BSTR + c]);
                b2[nt][0] = __float_as_uint(B2b[(8 * s + tig) * BSTR + c]);
                b2[nt][1] = __float_as_uint(B2b[(8 * s + 4 + tig) * BSTR + c]);
            }
            #pragma unroll
            for (int mt = 0; mt < 2; mt++)
                #pragma unroll
                for (int nt = 0; nt < 2; nt++) {
                    mma_tf32(acc1[mt][nt], ua[mt], b1[nt]);
                    mma_tf32(acc2[mt][nt], ua[mt], b2[nt]);
                }
        }
        bar_sync(barid, 256);
    }

    #pragma unroll
    for (int mt = 0; mt < 2; mt++) {
        const int r0 = bm + warpRow + mt * 16 + g;
        #pragma unroll
        for (int nt = 0; nt < 2; nt++) {
            const int col = bn + warpCol + nt * 8 + 2 * tig;
            #pragma unroll
            for (int half = 0; half < 2; half++) {
                const int row = r0 + half * 8;
                const float a0 = acc1[mt][nt][half * 2 + 0];
                const float a1 = acc1[mt][nt][half * 2 + 1];
                float2 o;
                o.x = a0 / (1.f + __expf(-a0)) * acc2[mt][nt][half * 2 + 0];
                o.y = a1 / (1.f + __expf(-a1)) * acc2[mt][nt][half * 2 + 1];
                *(float2*)&C[(size_t)row * N + col] = o;
            }
        }
    }
}

// ---------------- persistent mega-kernel -------------------------------------
__global__ __launch_bounds__(NTHR) void mega_k(
    const float* __restrict__ x,
    const float* __restrict__ n1w, const float* __restrict__ n2w,
    const float* __restrict__ wq, const float* __restrict__ bq,
    const float* __restrict__ wk, const float* __restrict__ bk,
    const float* __restrict__ wv, const float* __restrict__ bv,
    const float* __restrict__ wo, const float* __restrict__ bo,
    const float* __restrict__ w1, const float* __restrict__ w2,
    const float* __restrict__ w3,
    float* __restrict__ out) {

    extern __shared__ float dsm[];
    __shared__ int nbase[128];

    const int tid = threadIdx.x;
    const int bid = blockIdx.x;
    const int wg    = tid >> 7;        // warpgroup 0..3 (128 thr)
    const int tid_l = tid & 127;
    float* wsm = dsm + wg * GEMM_WG_FLOATS;

    // ---- phase 0: rms scales of x (one warp per token) ----
    {
        const int gw = bid * 16 + (tid >> 5);
        if (gw < NTOK) {
            const int lane = tid & 31;
            const float4 a = *(const float4*)&x[(size_t)gw * DMODEL + lane * 4];
            const float4 b = *(const float4*)&x[(size_t)gw * DMODEL + 128 + lane * 4];
            float s = a.x * a.x + a.y * a.y + a.z * a.z + a.w * a.w
                    + b.x * b.x + b.y * b.y + b.z * b.z + b.w * b.w;
            #pragma unroll
            for (int o = 16; o; o >>= 1) s += __shfl_xor_sync(0xffffffffu, s, o);
            if (lane == 0) g_rs1[gw] = rsqrtf(s * (1.0f / DMODEL) + 1e-6f);
        }
    }
    grid_sync(0);

    // ---- phase 1: QKV (768 tiles over 592 warpgroup slots) ----
    for (int t = bid * 4 + wg; t < 768; t += NBLK * 4) {
        const int z = t >> 8, rem = t & 255;
        const float* B  = (z == 0) ? wq : (z == 1) ? wk : wv;
        const float* bi = (z == 0) ? bq : (z == 1) ? bk : bv;
        float* C        = (z == 0) ? g_q : (z == 1) ? g_k : g_v;
        gemm_tile<true>(rem & 3, rem >> 2, wg + 1, tid_l,
                        x, g_rs1, n1w, B, bi, nullptr, C, nullptr,
                        DMODEL, DMODEL, wsm);
    }
    grid_sync(1);

    // ---- phase 2: NA3D attention (1024 tiles, whole block each) ----
    {
        if (tid < 128) {
            int val;
            if (tid < NNBR) {
                const int mt = tid / 25, mh = (tid / 5) % 5, mw = tid % 5;
                val = (mt * 64 + mh * 8 + mw) | (mt << 16);
            } else val = (-8) << 16;
            nbase[tid] = val;
        }
        __syncthreads();

        const int warp = tid >> 5;
        const int lane = tid & 31;
        const int gg   = lane >> 3;
        const int sub  = lane & 7;
        const float scale = 0.17677669529663687f;

        for (int tt = bid; tt < 1024; tt += NBLK) {
            const int head = tt >> 7;
            const int tile = tt & 127;
            const int t  = tile >> 4;
            const int hh = (tile >> 2) & 3;
            const int ww = tile & 3;
            const int tile_h0 = hh * 4, tile_w0 = ww * 4;
            const int h_base = min(max(tile_h0 - 2, 0), 8);
            const int w_base = min(max(tile_w0 - 2, 0), 8);

            const int h = tile_h0 + (warp >> 2);
            const int w = tile_w0 + (warp & 3);
            const int token = (t * 16 + h) * 16 + w;
            const int hoff = min(max(h - 2, 0), 11) - h_base;
            const int woff = min(max(w - 2, 0), 11) - w_base;
            const int sbase = hoff * 8 + woff;

            #pragma unroll
            for (int j = 0; j < 5; j++) {
                const int c = tid + 512 * j;
                const int slot = c >> 3, s8 = c & 7;
                const int tl = slot >> 6, rem = slot & 63;
                const int tn = max(t - 4 + tl, 0);
                const int hn = h_base + (rem >> 3), wn = w_base + (rem & 7);
                const float4 kv = *(const float4*)&g_k[(size_t)((tn * 16 + hn) * 16 + wn) * DMODEL + head * DHEAD + s8 * 4];
                *(float4*)&dsm[slot * 32 + s8 * 4] = kv;
            }
            const float4 q4 = *(const float4*)&g_q[(size_t)token * DMODEL + head * DHEAD + sub * 4];
            __syncthreads();

            float lg[32];
            #pragma unroll
            for (int i = 0; i < 32; i++) {
                const int m   = i * 4 + gg;
                const int val = nbase[m];
                const int slot = (val & 0xFFFF) + sbase;
                const int mt   = val >> 16;
                const float4 kv = *(const float4*)&dsm[slot * 32 + sub * 4];
                float d = q4.x * kv.x + q4.y * kv.y + q4.z * kv.z + q4.w * kv.w;
                d += __shfl_xor_sync(0xffffffffu, d, 1);
                d += __shfl_xor_sync(0xffffffffu, d, 2);
                d += __shfl_xor_sync(0xffffffffu, d, 4);
                lg[i] = (t - 4 + mt >= 0) ? d * scale : -INFINITY;
            }

            float mx = -INFINITY;
            #pragma unroll
            for (int i = 0; i < 32; i++) mx = fmaxf(mx, lg[i]);
            #pragma unroll
            for (int o = 16; o; o >>= 1) mx = fmaxf(mx, __shfl_xor_sync(0xffffffffu, mx, o));
            float sum = 0.f;
            #pragma unroll
            for (int i = 0; i < 32; i++) { lg[i] = __expf(lg[i] - mx); sum += lg[i]; }
            sum += __shfl_xor_sync(0xffffffffu, sum, 8);
            sum += __shfl_xor_sync(0xffffffffu, sum, 16);
            const float inv = 1.f / sum;

            __syncthreads();
            #pragma unroll
            for (int j = 0; j < 5; j++) {
                const int c = tid + 512 * j;
                const int slot = c >> 3, s8 = c & 7;
                const int tl = slot >> 6, rem = slot & 63;
                const int tn = max(t - 4 + tl, 0);
                const int hn = h_base + (rem >> 3), wn = w_base + (rem & 7);
                const float4 vv = *(const float4*)&g_v[(size_t)((tn * 16 + hn) * 16 + wn) * DMODEL + head * DHEAD + s8 * 4];
                *(float4*)&dsm[slot * 32 + s8 * 4] = vv;
            }
            __syncthreads();

            float4 acc = make_float4(0.f, 0.f, 0.f, 0.f);
            #pragma unroll
            for (int i = 0; i < 32; i++) {
                const int m    = i * 4 + gg;
                const int slot = (nbase[m] & 0xFFFF) + sbase;
                const float4 vv = *(const float4*)&dsm[slot * 32 + sub * 4];
                const float p = lg[i];
                acc.x = fmaf(p, vv.x, acc.x);
                acc.y = fmaf(p, vv.y, acc.y);
                acc.z = fmaf(p, vv.z, acc.z);
                acc.w = fmaf(p, vv.w, acc.w);
            }
            #pragma unroll
            for (int o = 8; o <= 16; o <<= 1) {
                acc.x += __shfl_xor_sync(0xffffffffu, acc.x, o);
                acc.y += __shfl_xor_sync(0xffffffffu, acc.y, o);
                acc.z += __shfl_xor_sync(0xffffffffu, acc.z, o);
                acc.w += __shfl_xor_sync(0xffffffffu, acc.w, o);
            }
            if (gg == 0) {
                float4 o4 = make_float4(acc.x * inv, acc.y * inv, acc.z * inv, acc.w * inv);
                *(float4*)&g_at[(size_t)token * DMODEL + head * DHEAD + sub * 4] = o4;
            }
            __syncthreads();
        }
    }
    grid_sync(2);

    // ---- phase 3: h = x + at @ wo + bo  (+ sumsq partials) ----
    for (int t = bid * 4 + wg; t < 256; t += NBLK * 4) {
        gemm_tile<false>(t & 3, t >> 2, wg + 1, tid_l,
                         g_at, nullptr, nullptr, wo, bo, x, g_h, g_ssp,
                         DMODEL, DMODEL, wsm);
    }
    grid_sync(3);

    // ---- phase 4: fa = silu(rmsnorm(h)@w1) * (rmsnorm(h)@w2) ----
    {
        const int grp = tid >> 8;          // 0..1 (256 thr)
        const int tid_g = tid & 255;
        float* gsm = dsm + grp * GATE_GR_FLOATS;
        for (int t = bid * 2 + grp; t < 512; t += NBLK * 2) {
            gate_tile(t & 15, t >> 4, 1 + grp, tid_g,
                      g_h, g_ssp, n2w, w1, w2, g_fa, DFF, DMODEL, gsm);
        }
    }
    grid_sync(4);

    // ---- phase 5: out = h + fa @ w3 ----
    for (int t = bid * 4 + wg; t < 256; t += NBLK * 4) {
        gemm_tile<false>(t & 3, t >> 2, wg + 1, tid_l,
                         g_fa, nullptr, nullptr, w3, nullptr, g_h, out, nullptr,
                         DMODEL, DFF, wsm);
    }
}

// ---------------- launch ------------------------------------------------------
extern "C" void kernel_launch(void* const* d_in, const int* in_sizes, int n_in,
                              void* d_out, int out_size) {
    const float* x   = (const float*)d_in[0];
    const float* n1w = (const float*)d_in[1];
    const float* n2w = (const float*)d_in[2];
    const float* wq  = (const float*)d_in[3];
    const float* bq  = (const float*)d_in[4];
    const float* wk  = (const float*)d_in[5];
    const float* bk  = (const float*)d_in[6];
    const float* wv  = (const float*)d_in[7];
    const float* bv  = (const float*)d_in[8];
    const float* wo  = (const float*)d_in[9];
    const float* bo  = (const float*)d_in[10];
    const float* w1  = (const float*)d_in[11];
    const float* w2  = (const float*)d_in[12];
    const float* w3  = (const float*)d_in[13];
    float* out = (float*)d_out;

    const int smem_bytes = SMEM_FLOATS * 4;   // 170496
    static int configured = 0;
    if (!configured) {
        cudaFuncSetAttribute(mega_k, cudaFuncAttributeMaxDynamicSharedMemorySize, smem_bytes);
        configured = 1;
    }

    mega_k<<<NBLK, NTHR, smem_bytes>>>(
        x, n1w, n2w, wq, bq, wk, bk, wv, bv, wo, bo, w1, w2, w3, out);
}